// round 2
// baseline (speedup 1.0000x reference)
#include <cuda_runtime.h>
#include <math.h>

// Problem constants
#define BB 2
#define NN 2048
#define CC 1024
#define HH 16
#define HD 64
#define GH 256
#define C3 3072
#define TOK (BB*NN)   // 4096

// Scratch (device globals: allocation-free)
__device__ float g_qkv[(size_t)TOK * C3];   // (B,N,3C)  48 MB
__device__ float g_att[(size_t)TOK * CC];   // (B,N,C)   16 MB
__device__ float g_gate[TOK];               // per (b, key)

// ---------------------------------------------------------------------------
// Gate MLP: gate[b,n] = sigmoid( relu(m*g1_w + g1_b) @ g2_w + g2_b )
// ---------------------------------------------------------------------------
__global__ void gate_kernel(const float* __restrict__ sm,
                            const float* __restrict__ g1w,
                            const float* __restrict__ g1b,
                            const float* __restrict__ g2w,
                            const float* __restrict__ g2b) {
    int idx = blockIdx.x * blockDim.x + threadIdx.x;
    if (idx >= TOK) return;
    float m = sm[idx];
    float acc = g2b[0];
#pragma unroll 8
    for (int j = 0; j < GH; ++j) {
        float h = fmaf(m, g1w[j], g1b[j]);
        h = fmaxf(h, 0.f);
        acc = fmaf(h, g2w[j], acc);
    }
    g_gate[idx] = 1.f / (1.f + __expf(-acc));
}

// ---------------------------------------------------------------------------
// Generic C[m,n] = sum_k A[m,k]*W[n,k] + bias[n]   (A: MxK, W: NxK, row-major)
// 64x64 tile, BK=16, 256 threads, 4x4 per-thread microtile.
// ---------------------------------------------------------------------------
#define BM 64
#define BNT 64
#define BKK 16

__global__ void gemm_nt_bias(const float* __restrict__ A,
                             const float* __restrict__ W,
                             const float* __restrict__ bias,
                             float* __restrict__ Cout,
                             int M, int Nn, int K) {
    __shared__ float As[BKK][BM + 1];
    __shared__ float Ws[BKK][BNT + 1];
    int tid = threadIdx.x;
    int bm = blockIdx.y * BM, bn = blockIdx.x * BNT;
    int ty = tid >> 4, tx = tid & 15;
    int lr = tid >> 2;           // 0..63
    int lk = (tid & 3) << 2;     // 0,4,8,12
    float acc[4][4] = {};

    for (int k0 = 0; k0 < K; k0 += BKK) {
        float4 a = *(const float4*)(A + (size_t)(bm + lr) * K + k0 + lk);
        float4 w = *(const float4*)(W + (size_t)(bn + lr) * K + k0 + lk);
        As[lk + 0][lr] = a.x; As[lk + 1][lr] = a.y;
        As[lk + 2][lr] = a.z; As[lk + 3][lr] = a.w;
        Ws[lk + 0][lr] = w.x; Ws[lk + 1][lr] = w.y;
        Ws[lk + 2][lr] = w.z; Ws[lk + 3][lr] = w.w;
        __syncthreads();
#pragma unroll
        for (int kk = 0; kk < BKK; ++kk) {
            float av[4], wv[4];
#pragma unroll
            for (int i = 0; i < 4; ++i) av[i] = As[kk][ty * 4 + i];
#pragma unroll
            for (int j = 0; j < 4; ++j) wv[j] = Ws[kk][tx * 4 + j];
#pragma unroll
            for (int i = 0; i < 4; ++i)
#pragma unroll
                for (int j = 0; j < 4; ++j)
                    acc[i][j] = fmaf(av[i], wv[j], acc[i][j]);
        }
        __syncthreads();
    }
#pragma unroll
    for (int i = 0; i < 4; ++i) {
        int row = bm + ty * 4 + i;
#pragma unroll
        for (int j = 0; j < 4; ++j) {
            int col = bn + tx * 4 + j;
            Cout[(size_t)row * Nn + col] = acc[i][j] + bias[col];
        }
    }
}

// ---------------------------------------------------------------------------
// Flash attention with per-key gate on the logits.
// Block = one (b,h) x 64-query tile. 256 threads, 4x4 microtiles.
// logit = (q.k * HD^-0.5) * gate[b,k]; online softmax over all 2048 keys.
// ---------------------------------------------------------------------------
#define TQ 64
#define TK 64
#define SPAD 65

__global__ void attn_kernel() {
    extern __shared__ float smem[];
    float* Qs   = smem;                 // [TQ][SPAD]  Qs[q*SPAD+d]
    float* Kst  = Qs  + TQ * SPAD;      // [HD][SPAD]  Kst[d*SPAD+k]  (transposed)
    float* Vs   = Kst + HD * SPAD;      // [TK][SPAD]  Vs[k*SPAD+d]
    float* Ss   = Vs  + TK * SPAD;      // [TQ][SPAD]  scores / probs
    float* rmax = Ss  + TQ * SPAD;      // [TQ]
    float* rsum = rmax + TQ;            // [TQ]
    float* gs   = rsum + TQ;            // [TK] gate, reused as corr[TQ]

    int tid = threadIdx.x;
    int bh = blockIdx.y;
    int b = bh / HH, h = bh % HH;
    int q0 = blockIdx.x * TQ;
    int ty = tid >> 4, tx = tid & 15;
    const float scale = 0.125f;  // HD^-0.5

    // Load Q tile once
    for (int idx = tid; idx < TQ * HD; idx += 256) {
        int q = idx >> 6, d = idx & 63;
        Qs[q * SPAD + d] = g_qkv[(size_t)(b * NN + q0 + q) * C3 + h * HD + d];
    }
    if (tid < TQ) { rmax[tid] = -1e30f; rsum[tid] = 0.f; }
    float o[4][4] = {};
    __syncthreads();

    for (int kt = 0; kt < NN; kt += TK) {
        // Load K (transposed to [d][k]) and V tiles + gate
        for (int idx = tid; idx < TK * HD; idx += 256) {
            int kl = idx >> 6, d = idx & 63;
            size_t base = (size_t)(b * NN + kt + kl) * C3 + h * HD + d;
            Kst[d * SPAD + kl] = g_qkv[base + CC];
            Vs[kl * SPAD + d]  = g_qkv[base + 2 * CC];
        }
        if (tid < TK) gs[tid] = g_gate[b * NN + kt + tid];
        __syncthreads();

        // S = Q @ K^T, apply scale * gate[key]
        {
            float s[4][4] = {};
#pragma unroll 8
            for (int d = 0; d < HD; ++d) {
                float qv[4], kv[4];
#pragma unroll
                for (int i = 0; i < 4; ++i) qv[i] = Qs[(ty * 4 + i) * SPAD + d];
#pragma unroll
                for (int j = 0; j < 4; ++j) kv[j] = Kst[d * SPAD + tx * 4 + j];
#pragma unroll
                for (int i = 0; i < 4; ++i)
#pragma unroll
                    for (int j = 0; j < 4; ++j)
                        s[i][j] = fmaf(qv[i], kv[j], s[i][j]);
            }
#pragma unroll
            for (int i = 0; i < 4; ++i)
#pragma unroll
                for (int j = 0; j < 4; ++j)
                    Ss[(ty * 4 + i) * SPAD + tx * 4 + j] =
                        s[i][j] * scale * gs[tx * 4 + j];
        }
        __syncthreads();

        // Online softmax state update (one thread per query row)
        if (tid < TQ) {
            int r = tid;
            float mx = rmax[r];
#pragma unroll 8
            for (int k = 0; k < TK; ++k) mx = fmaxf(mx, Ss[r * SPAD + k]);
            float corr = __expf(rmax[r] - mx);
            float sum = rsum[r] * corr;
#pragma unroll 8
            for (int k = 0; k < TK; ++k) {
                float p = __expf(Ss[r * SPAD + k] - mx);
                Ss[r * SPAD + k] = p;
                sum += p;
            }
            rmax[r] = mx;
            rsum[r] = sum;
            gs[r] = corr;   // gate no longer needed this tile; reuse as corr
        }
        __syncthreads();

        // O = O*corr + P @ V
        {
            float cr[4];
#pragma unroll
            for (int i = 0; i < 4; ++i) cr[i] = gs[ty * 4 + i];
#pragma unroll
            for (int i = 0; i < 4; ++i)
#pragma unroll
                for (int j = 0; j < 4; ++j) o[i][j] *= cr[i];
#pragma unroll 8
            for (int k = 0; k < TK; ++k) {
                float pv[4], vv[4];
#pragma unroll
                for (int i = 0; i < 4; ++i) pv[i] = Ss[(ty * 4 + i) * SPAD + k];
#pragma unroll
                for (int j = 0; j < 4; ++j) vv[j] = Vs[k * SPAD + tx * 4 + j];
#pragma unroll
                for (int i = 0; i < 4; ++i)
#pragma unroll
                    for (int j = 0; j < 4; ++j)
                        o[i][j] = fmaf(pv[i], vv[j], o[i][j]);
            }
        }
        __syncthreads();
    }

    // Normalize and write to (B,N,C) layout for the proj GEMM
    float inv[4];
#pragma unroll
    for (int i = 0; i < 4; ++i) inv[i] = 1.f / rsum[ty * 4 + i];
#pragma unroll
    for (int i = 0; i < 4; ++i)
#pragma unroll
        for (int j = 0; j < 4; ++j)
            g_att[(size_t)(b * NN + q0 + ty * 4 + i) * CC + h * HD + tx * 4 + j] =
                o[i][j] * inv[i];
}

// ---------------------------------------------------------------------------
// Launch
// ---------------------------------------------------------------------------
extern "C" void kernel_launch(void* const* d_in, const int* in_sizes, int n_in,
                              void* d_out, int out_size) {
    (void)in_sizes; (void)n_in; (void)out_size;
    const float* x      = (const float*)d_in[0];
    const float* smask  = (const float*)d_in[1];
    const float* qkv_w  = (const float*)d_in[2];
    const float* qkv_b  = (const float*)d_in[3];
    const float* proj_w = (const float*)d_in[4];
    const float* proj_b = (const float*)d_in[5];
    const float* g1_w   = (const float*)d_in[6];
    const float* g1_b   = (const float*)d_in[7];
    const float* g2_w   = (const float*)d_in[8];
    const float* g2_b   = (const float*)d_in[9];
    float* out = (float*)d_out;

    float *qkv_p, *att_p;
    cudaGetSymbolAddress((void**)&qkv_p, g_qkv);
    cudaGetSymbolAddress((void**)&att_p, g_att);

    // 1. gate
    gate_kernel<<<(TOK + 255) / 256, 256>>>(smask, g1_w, g1_b, g2_w, g2_b);

    // 2. qkv = x @ qkv_w^T + qkv_b   (4096 x 3072, K=1024)
    gemm_nt_bias<<<dim3(C3 / BNT, TOK / BM), 256>>>(x, qkv_w, qkv_b, qkv_p,
                                                    TOK, C3, CC);

    // 3. attention (flash, gated logits)
    const int smem_bytes = (TQ * SPAD + HD * SPAD + TK * SPAD + TQ * SPAD
                            + TQ + TQ + TK) * (int)sizeof(float);
    cudaFuncSetAttribute(attn_kernel,
                         cudaFuncAttributeMaxDynamicSharedMemorySize, smem_bytes);
    attn_kernel<<<dim3(NN / TQ, BB * HH), 256, smem_bytes>>>();

    // 4. out = att @ proj_w^T + proj_b   (4096 x 1024, K=1024)
    gemm_nt_bias<<<dim3(CC / BNT, TOK / BM), 256>>>(att_p, proj_w, proj_b, out,
                                                    TOK, CC, CC);
}

// round 4
// speedup vs baseline: 3.4251x; 3.4251x over previous
#include <cuda_runtime.h>
#include <cuda_bf16.h>
#include <cstdint>
#include <math.h>

// Problem constants
#define BB 2
#define NN 2048
#define CC 1024
#define HH 16
#define HD 64
#define GH 256
#define C3 3072
#define TOK (BB*NN)   // 4096

// Scratch (device globals: allocation-free)
__device__ float g_qkv[(size_t)TOK * C3];   // (B,N,3C)  48 MB
__device__ float g_att[(size_t)TOK * CC];   // (B,N,C)   16 MB
__device__ float g_gate[TOK];               // per (b, key)

// ---------------------------------------------------------------------------
// Helpers (baseline PTX only: ldmatrix sm_75, mma.sync bf16 sm_80)
// ---------------------------------------------------------------------------
__device__ __forceinline__ uint32_t smem_u32(const void* p) {
    uint32_t a;
    asm("{ .reg .u64 t; cvta.to.shared.u64 t, %1; cvt.u32.u64 %0, t; }"
        : "=r"(a) : "l"(p));
    return a;
}
__device__ __forceinline__ void ldsm4(uint32_t* r, uint32_t addr) {
    asm volatile("ldmatrix.sync.aligned.m8n8.x4.shared.b16 {%0,%1,%2,%3}, [%4];"
                 : "=r"(r[0]), "=r"(r[1]), "=r"(r[2]), "=r"(r[3]) : "r"(addr));
}
__device__ __forceinline__ void ldsm4t(uint32_t* r, uint32_t addr) {
    asm volatile("ldmatrix.sync.aligned.m8n8.x4.trans.shared.b16 {%0,%1,%2,%3}, [%4];"
                 : "=r"(r[0]), "=r"(r[1]), "=r"(r[2]), "=r"(r[3]) : "r"(addr));
}
__device__ __forceinline__ void mma16816(float* d, const uint32_t* a,
                                         uint32_t b0, uint32_t b1) {
    asm volatile(
        "mma.sync.aligned.m16n8k16.row.col.f32.bf16.bf16.f32 "
        "{%0,%1,%2,%3}, {%4,%5,%6,%7}, {%8,%9}, {%0,%1,%2,%3};"
        : "+f"(d[0]), "+f"(d[1]), "+f"(d[2]), "+f"(d[3])
        : "r"(a[0]), "r"(a[1]), "r"(a[2]), "r"(a[3]), "r"(b0), "r"(b1));
}
// Split (x,y) fp32 pair into bf16x2 hi + bf16x2 lo (hi+lo ~ 17-bit mantissa)
__device__ __forceinline__ void pack2(float x, float y, uint32_t& hi, uint32_t& lo) {
    __nv_bfloat162 h = __floats2bfloat162_rn(x, y);
    float2 hf = __bfloat1622float2(h);
    __nv_bfloat162 l = __floats2bfloat162_rn(x - hf.x, y - hf.y);
    hi = *reinterpret_cast<uint32_t*>(&h);
    lo = *reinterpret_cast<uint32_t*>(&l);
}
__device__ __forceinline__ void split4(float4 v, uint32_t& h0, uint32_t& h1,
                                       uint32_t& l0, uint32_t& l1) {
    pack2(v.x, v.y, h0, l0);
    pack2(v.z, v.w, h1, l1);
}

// ---------------------------------------------------------------------------
// Gate MLP
// ---------------------------------------------------------------------------
__global__ void gate_kernel(const float* __restrict__ sm,
                            const float* __restrict__ g1w,
                            const float* __restrict__ g1b,
                            const float* __restrict__ g2w,
                            const float* __restrict__ g2b) {
    int idx = blockIdx.x * blockDim.x + threadIdx.x;
    if (idx >= TOK) return;
    float m = sm[idx];
    float acc = g2b[0];
#pragma unroll 8
    for (int j = 0; j < GH; ++j) {
        float h = fmaf(m, g1w[j], g1b[j]);
        h = fmaxf(h, 0.f);
        acc = fmaf(h, g2w[j], acc);
    }
    g_gate[idx] = 1.f / (1.f + __expf(-acc));
}

// ---------------------------------------------------------------------------
// HMMA split-bf16 GEMM: C[m,n] = sum_k A[m,k]*W[n,k] + bias[n]
// Block 128x128, BK=32, 8 warps (2x4), warp tile 64x32.
// ---------------------------------------------------------------------------
#define GBK 32
#define GSTR 40   // bf16 row stride (32 data + 8 pad) -> 80B, conflict-free ldsm

__global__ void __launch_bounds__(256) gemm_mma(const float* __restrict__ A,
                                                const float* __restrict__ W,
                                                const float* __restrict__ bias,
                                                float* __restrict__ Cout,
                                                int Nn, int K) {
    __shared__ __align__(16) __nv_bfloat16 sAh[128 * GSTR], sAl[128 * GSTR];
    __shared__ __align__(16) __nv_bfloat16 sBh[128 * GSTR], sBl[128 * GSTR];
    int tid = threadIdx.x, lane = tid & 31, wid = tid >> 5;
    int wm = wid >> 2, wn = wid & 3;
    int bm = blockIdx.y * 128, bn = blockIdx.x * 128;
    uint32_t uAh = smem_u32(sAh), uAl = smem_u32(sAl);
    uint32_t uBh = smem_u32(sBh), uBl = smem_u32(sBl);

    float acc[4][4][4] = {};
    int lrow = tid >> 3, lcol = (tid & 7) * 4;

    for (int k0 = 0; k0 < K; k0 += GBK) {
#pragma unroll
        for (int i = 0; i < 4; ++i) {
            int row = lrow + 32 * i;
            uint32_t h0, h1, l0, l1;
            float4 va = *(const float4*)(A + (size_t)(bm + row) * K + k0 + lcol);
            split4(va, h0, h1, l0, l1);
            *(uint2*)(sAh + row * GSTR + lcol) = make_uint2(h0, h1);
            *(uint2*)(sAl + row * GSTR + lcol) = make_uint2(l0, l1);
            float4 vb = *(const float4*)(W + (size_t)(bn + row) * K + k0 + lcol);
            split4(vb, h0, h1, l0, l1);
            *(uint2*)(sBh + row * GSTR + lcol) = make_uint2(h0, h1);
            *(uint2*)(sBl + row * GSTR + lcol) = make_uint2(l0, l1);
        }
        __syncthreads();
#pragma unroll
        for (int kk = 0; kk < 2; ++kk) {
            uint32_t cb = kk * 16 + (lane >> 4) * 8;   // k-col block (elems)
            uint32_t bh[2][4], bl[2][4];
#pragma unroll
            for (int bt = 0; bt < 2; ++bt) {
                uint32_t ro = (wn * 32 + bt * 16 + (lane & 15)) * GSTR + cb;
                ldsm4(bh[bt], uBh + 2 * ro);
                ldsm4(bl[bt], uBl + 2 * ro);
            }
#pragma unroll
            for (int mi = 0; mi < 4; ++mi) {
                uint32_t ro = (wm * 64 + mi * 16 + (lane & 15)) * GSTR + cb;
                uint32_t ah[4], al[4];
                ldsm4(ah, uAh + 2 * ro);
                ldsm4(al, uAl + 2 * ro);
#pragma unroll
                for (int bt = 0; bt < 2; ++bt) {
                    // even n-tile: {r0,r2}; odd n-tile: {r1,r3}
                    mma16816(acc[mi][2 * bt],     ah, bh[bt][0], bh[bt][2]);
                    mma16816(acc[mi][2 * bt],     ah, bl[bt][0], bl[bt][2]);
                    mma16816(acc[mi][2 * bt],     al, bh[bt][0], bh[bt][2]);
                    mma16816(acc[mi][2 * bt + 1], ah, bh[bt][1], bh[bt][3]);
                    mma16816(acc[mi][2 * bt + 1], ah, bl[bt][1], bl[bt][3]);
                    mma16816(acc[mi][2 * bt + 1], al, bh[bt][1], bh[bt][3]);
                }
            }
        }
        __syncthreads();
    }
    // epilogue: C frag (r, 2q) pairs
    int r = lane >> 2, c2 = (lane & 3) * 2;
#pragma unroll
    for (int mi = 0; mi < 4; ++mi) {
        int row0 = bm + wm * 64 + mi * 16 + r;
#pragma unroll
        for (int ni = 0; ni < 4; ++ni) {
            int col = bn + wn * 32 + ni * 8 + c2;
            float2 b2 = {bias[col], bias[col + 1]};
            float2 o0 = {acc[mi][ni][0] + b2.x, acc[mi][ni][1] + b2.y};
            float2 o1 = {acc[mi][ni][2] + b2.x, acc[mi][ni][3] + b2.y};
            *(float2*)(Cout + (size_t)row0 * Nn + col) = o0;
            *(float2*)(Cout + (size_t)(row0 + 8) * Nn + col) = o1;
        }
    }
}

// ---------------------------------------------------------------------------
// Flash attention, HMMA split-bf16, gated logits.
// Block = (b,h) x 64-query tile, 4 warps (one 16-row band each), keys in
// tiles of 64. Q/K/V split hi/lo in smem; S and O stay in mma fragments.
// ---------------------------------------------------------------------------
#define ATSTR 72  // 64 data + 8 pad bf16 -> 144B rows, conflict-free ldsm
#define ATN_SMEM (6 * 64 * ATSTR * 2 + 64 * 4)

__global__ void __launch_bounds__(128) attn_mma() {
    extern __shared__ __align__(16) char smc[];
    __nv_bfloat16* sQh = (__nv_bfloat16*)smc;
    __nv_bfloat16* sQl = sQh + 64 * ATSTR;
    __nv_bfloat16* sKh = sQl + 64 * ATSTR;
    __nv_bfloat16* sKl = sKh + 64 * ATSTR;
    __nv_bfloat16* sVh = sKl + 64 * ATSTR;
    __nv_bfloat16* sVl = sVh + 64 * ATSTR;
    float* gs = (float*)(sVl + 64 * ATSTR);

    int tid = threadIdx.x, lane = tid & 31, wid = tid >> 5;
    int bhid = blockIdx.y;
    int b = bhid >> 4, h = bhid & 15;
    int q0 = blockIdx.x * 64;
    uint32_t uQh = smem_u32(sQh), uQl = smem_u32(sQl);
    uint32_t uKh = smem_u32(sKh), uKl = smem_u32(sKl);
    uint32_t uVh = smem_u32(sVh), uVl = smem_u32(sVl);

    int lrow = tid >> 4, lcol = (tid & 15) * 4;
    // Load + split Q (64x64)
#pragma unroll
    for (int i = 0; i < 8; ++i) {
        int row = lrow + 8 * i;
        float4 v = *(const float4*)&g_qkv[(size_t)(b * NN + q0 + row) * C3 + h * HD + lcol];
        uint32_t h0, h1, l0, l1;
        split4(v, h0, h1, l0, l1);
        *(uint2*)(sQh + row * ATSTR + lcol) = make_uint2(h0, h1);
        *(uint2*)(sQl + row * ATSTR + lcol) = make_uint2(l0, l1);
    }

    float m0 = -1e30f, m1 = -1e30f, l0s = 0.f, l1s = 0.f;
    float o[8][4] = {};

    for (int kt = 0; kt < NN; kt += 64) {
#pragma unroll
        for (int i = 0; i < 8; ++i) {
            int row = lrow + 8 * i;
            size_t base = (size_t)(b * NN + kt + row) * C3 + h * HD + lcol;
            uint32_t h0, h1, l0, l1;
            float4 vk = *(const float4*)&g_qkv[base + CC];
            split4(vk, h0, h1, l0, l1);
            *(uint2*)(sKh + row * ATSTR + lcol) = make_uint2(h0, h1);
            *(uint2*)(sKl + row * ATSTR + lcol) = make_uint2(l0, l1);
            float4 vv = *(const float4*)&g_qkv[base + 2 * CC];
            split4(vv, h0, h1, l0, l1);
            *(uint2*)(sVh + row * ATSTR + lcol) = make_uint2(h0, h1);
            *(uint2*)(sVl + row * ATSTR + lcol) = make_uint2(l0, l1);
        }
        if (tid < 64) gs[tid] = g_gate[b * NN + kt + tid];
        __syncthreads();

        // ---- S = Q @ K^T (keys = mma n dim) ----
        float S[8][4] = {};
#pragma unroll
        for (int kk = 0; kk < 4; ++kk) {
            uint32_t cb = kk * 16 + (lane >> 4) * 8;
            uint32_t qro = (wid * 16 + (lane & 15)) * ATSTR + cb;
            uint32_t qh[4], ql[4];
            ldsm4(qh, uQh + 2 * qro);
            ldsm4(ql, uQl + 2 * qro);
#pragma unroll
            for (int nt2 = 0; nt2 < 4; ++nt2) {
                uint32_t kro = (nt2 * 16 + (lane & 15)) * ATSTR + cb;
                uint32_t kh[4], kl[4];
                ldsm4(kh, uKh + 2 * kro);
                ldsm4(kl, uKl + 2 * kro);
                mma16816(S[2 * nt2],     qh, kh[0], kh[2]);
                mma16816(S[2 * nt2],     qh, kl[0], kl[2]);
                mma16816(S[2 * nt2],     ql, kh[0], kh[2]);
                mma16816(S[2 * nt2 + 1], qh, kh[1], kh[3]);
                mma16816(S[2 * nt2 + 1], qh, kl[1], kl[3]);
                mma16816(S[2 * nt2 + 1], ql, kh[1], kh[3]);
            }
        }
        // ---- scale * gate[key] ----
        int kc = (lane & 3) * 2;
#pragma unroll
        for (int nt = 0; nt < 8; ++nt) {
            float ga = gs[nt * 8 + kc] * 0.125f;
            float gb = gs[nt * 8 + kc + 1] * 0.125f;
            S[nt][0] *= ga; S[nt][1] *= gb;
            S[nt][2] *= ga; S[nt][3] *= gb;
        }
        // ---- online softmax ----
        float mx0 = m0, mx1 = m1;
#pragma unroll
        for (int nt = 0; nt < 8; ++nt) {
            mx0 = fmaxf(mx0, fmaxf(S[nt][0], S[nt][1]));
            mx1 = fmaxf(mx1, fmaxf(S[nt][2], S[nt][3]));
        }
        mx0 = fmaxf(mx0, __shfl_xor_sync(0xffffffffu, mx0, 1));
        mx0 = fmaxf(mx0, __shfl_xor_sync(0xffffffffu, mx0, 2));
        mx1 = fmaxf(mx1, __shfl_xor_sync(0xffffffffu, mx1, 1));
        mx1 = fmaxf(mx1, __shfl_xor_sync(0xffffffffu, mx1, 2));
        float c0 = __expf(m0 - mx0), c1 = __expf(m1 - mx1);
        m0 = mx0; m1 = mx1;
        l0s *= c0; l1s *= c1;
#pragma unroll
        for (int dt = 0; dt < 8; ++dt) {
            o[dt][0] *= c0; o[dt][1] *= c0;
            o[dt][2] *= c1; o[dt][3] *= c1;
        }
        float s0 = 0.f, s1 = 0.f;
#pragma unroll
        for (int nt = 0; nt < 8; ++nt) {
            S[nt][0] = __expf(S[nt][0] - mx0); s0 += S[nt][0];
            S[nt][1] = __expf(S[nt][1] - mx0); s0 += S[nt][1];
            S[nt][2] = __expf(S[nt][2] - mx1); s1 += S[nt][2];
            S[nt][3] = __expf(S[nt][3] - mx1); s1 += S[nt][3];
        }
        s0 += __shfl_xor_sync(0xffffffffu, s0, 1);
        s0 += __shfl_xor_sync(0xffffffffu, s0, 2);
        s1 += __shfl_xor_sync(0xffffffffu, s1, 1);
        s1 += __shfl_xor_sync(0xffffffffu, s1, 2);
        l0s += s0; l1s += s1;
        // ---- P (C-frag) -> A-frag repack, split hi/lo ----
        uint32_t ph[4][4], pl[4][4];
#pragma unroll
        for (int kb = 0; kb < 4; ++kb) {
            pack2(S[2 * kb][0],     S[2 * kb][1],     ph[kb][0], pl[kb][0]);
            pack2(S[2 * kb][2],     S[2 * kb][3],     ph[kb][1], pl[kb][1]);
            pack2(S[2 * kb + 1][0], S[2 * kb + 1][1], ph[kb][2], pl[kb][2]);
            pack2(S[2 * kb + 1][2], S[2 * kb + 1][3], ph[kb][3], pl[kb][3]);
        }
        // ---- O += P @ V  (ldmatrix.trans on V[k][d]) ----
#pragma unroll
        for (int kb = 0; kb < 4; ++kb) {
#pragma unroll
            for (int dt2 = 0; dt2 < 4; ++dt2) {
                uint32_t vro = (kb * 16 + (lane & 15)) * ATSTR
                             + dt2 * 16 + (lane >> 4) * 8;
                uint32_t vh[4], vl[4];
                ldsm4t(vh, uVh + 2 * vro);
                ldsm4t(vl, uVl + 2 * vro);
                // trans pairing: even d-tile {r0,r1}, odd {r2,r3}
                mma16816(o[2 * dt2],     ph[kb], vh[0], vh[1]);
                mma16816(o[2 * dt2],     ph[kb], vl[0], vl[1]);
                mma16816(o[2 * dt2],     pl[kb], vh[0], vh[1]);
                mma16816(o[2 * dt2 + 1], ph[kb], vh[2], vh[3]);
                mma16816(o[2 * dt2 + 1], ph[kb], vl[2], vl[3]);
                mma16816(o[2 * dt2 + 1], pl[kb], vh[2], vh[3]);
            }
        }
        __syncthreads();
    }

    float i0 = 1.f / l0s, i1 = 1.f / l1s;
    int r = lane >> 2, c2 = (lane & 3) * 2;
    int row0 = q0 + wid * 16 + r;
#pragma unroll
    for (int dt = 0; dt < 8; ++dt) {
        int d = dt * 8 + c2;
        float2 o0 = {o[dt][0] * i0, o[dt][1] * i0};
        float2 o1 = {o[dt][2] * i1, o[dt][3] * i1};
        *(float2*)&g_att[(size_t)(b * NN + row0) * CC + h * HD + d] = o0;
        *(float2*)&g_att[(size_t)(b * NN + row0 + 8) * CC + h * HD + d] = o1;
    }
}

// ---------------------------------------------------------------------------
// Launch
// ---------------------------------------------------------------------------
extern "C" void kernel_launch(void* const* d_in, const int* in_sizes, int n_in,
                              void* d_out, int out_size) {
    (void)in_sizes; (void)n_in; (void)out_size;
    const float* x      = (const float*)d_in[0];
    const float* smask  = (const float*)d_in[1];
    const float* qkv_w  = (const float*)d_in[2];
    const float* qkv_b  = (const float*)d_in[3];
    const float* proj_w = (const float*)d_in[4];
    const float* proj_b = (const float*)d_in[5];
    const float* g1_w   = (const float*)d_in[6];
    const float* g1_b   = (const float*)d_in[7];
    const float* g2_w   = (const float*)d_in[8];
    const float* g2_b   = (const float*)d_in[9];
    float* out = (float*)d_out;

    float *qkv_p, *att_p;
    cudaGetSymbolAddress((void**)&qkv_p, g_qkv);
    cudaGetSymbolAddress((void**)&att_p, g_att);

    // 1. gate
    gate_kernel<<<(TOK + 255) / 256, 256>>>(smask, g1_w, g1_b, g2_w, g2_b);

    // 2. qkv = x @ qkv_w^T + qkv_b
    gemm_mma<<<dim3(C3 / 128, TOK / 128), 256>>>(x, qkv_w, qkv_b, qkv_p, C3, CC);

    // 3. attention
    cudaFuncSetAttribute(attn_mma, cudaFuncAttributeMaxDynamicSharedMemorySize,
                         ATN_SMEM);
    attn_mma<<<dim3(NN / 64, BB * HH), 128, ATN_SMEM>>>();

    // 4. out = att @ proj_w^T + proj_b
    gemm_mma<<<dim3(CC / 128, TOK / 128), 256>>>(att_p, proj_w, proj_b, out, CC, CC);
}